// round 8
// baseline (speedup 1.0000x reference)
#include <cuda_runtime.h>
#include <cstdint>

// CharEmb via mma.sync m16n8k8 tf32, v4:
//   3 GEMMs sharing one B: Z_k[f][c'] = sum_i W_k[f][i] * G[i][c'] (K=64)
//   G[i][c'] = flat[i*32+c'],  flat[j] = emb[ids[j>>6]][j&63]
//   Y[f][t] = Z_0[t] + Z_1[t+1] + Z_2[t+2]; out = max_{t<30} Y + bias.
//  - A_k in registers (96 regs), loaded once from gmem.
//  - B fragments built ONCE per word into smem (cvt+indexing deduped across
//    warps), lane-contiguous 48B slots -> conflict-free LDS.128 reads.
//  - flat stride 36 (conflict-free build reads, float4-aligned stores).
//  - double-buffered flat/xfs, gather(w+2) + build(w+1) under MMA(w),
//    one __syncthreads per word. Shift-combine epilogue via quad shuffles.

static constexpr int WORDS   = 16384;
static constexpr int WPC     = 16;
static constexpr int GRID    = WORDS / WPC;   // 1024
static constexpr int THREADS = 256;           // 8 warps x 16 filters

static constexpr int FLAT_STRIDE = 36;                 // floats per G row
static constexpr int FLAT_SZ     = 64 * FLAT_STRIDE;   // 2304 floats
static constexpr int XFS_KT      = 32 * 48;            // bytes per kt (48B/lane)
static constexpr int XFS_BUF     = 8 * XFS_KT;         // 12288 B
static constexpr int FLAT_OFF    = 2 * XFS_BUF;        // 24576
static constexpr int SMEM_TOTAL  = FLAT_OFF + 2 * FLAT_SZ * 4;  // 43008 B

__device__ __forceinline__ uint32_t f2tf32(float f) {
    uint32_t r; asm("cvt.rn.tf32.f32 %0, %1;" : "=r"(r) : "f"(f)); return r;
}
struct U4 { uint32_t x, y, z, w; };

// one (kt, lane) fragment pair: b0[nt] = G[8kt+(l&3)][8nt+(l>>2)], b1 = +4 rows
__device__ __forceinline__ void build_pair(char* __restrict__ xbuf,
                                           const float* __restrict__ fl,
                                           int kt, int l) {
    const float* p0 = fl + (8 * kt + (l & 3)) * FLAT_STRIDE + (l >> 2);
    const float* p1 = p0 + 4 * FLAT_STRIDE;
    uint4 lo, hi;
    lo.x = f2tf32(p0[0]);  lo.y = f2tf32(p0[8]);
    lo.z = f2tf32(p0[16]); lo.w = f2tf32(p0[24]);
    hi.x = f2tf32(p1[0]);  hi.y = f2tf32(p1[8]);
    hi.z = f2tf32(p1[16]); hi.w = f2tf32(p1[24]);
    *(uint4*)(xbuf + kt * XFS_KT + l * 48)      = lo;
    *(uint4*)(xbuf + kt * XFS_KT + l * 48 + 16) = hi;
}

__global__ __launch_bounds__(THREADS, 1) void charconv_hmma4(
    const int* __restrict__ ids,    // [WORDS][32]
    const float* __restrict__ wg,   // [128][64][3]
    const float* __restrict__ emb,  // [101][64]
    const float* __restrict__ bias, // [128]
    float* __restrict__ out)        // [WORDS][128]
{
    extern __shared__ char smem[];
    float* flat = (float*)(smem + FLAT_OFF);

    const int tid  = threadIdx.x;
    const int wu   = tid >> 5, lane = tid & 31;
    const int q    = lane & 3, g = lane >> 2;
    const int word0 = blockIdx.x * WPC;

    // ---- gather word0 (issue LDG early, overlap with A-load) ----
    float4 gv[2];
    {
        const int* wid = ids + word0 * 32;
        #pragma unroll
        for (int j = 0; j < 2; j++) {
            int qq = tid + j * 256;
            gv[j] = *(const float4*)(emb + wid[qq >> 4] * 64 + ((qq * 4) & 63));
        }
    }

    // ---- A fragments: a[k][kt]; A_k[f][i] = wg[f*192 + i*3 + k] ----
    U4 a[3][8];
    {
        const float* r0 = wg + (wu * 16 + g) * 192 + q * 3;
        const float* r1 = r0 + 8 * 192;
        #pragma unroll
        for (int k = 0; k < 3; k++)
            #pragma unroll
            for (int kt = 0; kt < 8; kt++) {
                int o = 24 * kt + k;
                a[k][kt].x = f2tf32(r0[o]);
                a[k][kt].y = f2tf32(r1[o]);
                a[k][kt].z = f2tf32(r0[o + 12]);
                a[k][kt].w = f2tf32(r1[o + 12]);
            }
    }
    const float blo_b = bias[wu * 16 + g];
    const float bhi_b = bias[wu * 16 + g + 8];

    // flat[0] <- word0 (padded stride: float4 at i*36+c, c=el&31, i=el>>5)
    #pragma unroll
    for (int j = 0; j < 2; j++) {
        int qq = tid + j * 256, el = qq * 4;
        *(float4*)(flat + (el >> 5) * FLAT_STRIDE + (el & 31)) = gv[j];
    }
    __syncthreads();

    // build xfs[0]; gather word1 -> flat[1]
    build_pair(smem, flat, wu, lane);
    {
        const int* wid = ids + (word0 + 1) * 32;
        #pragma unroll
        for (int j = 0; j < 2; j++) {
            int qq = tid + j * 256;
            gv[j] = *(const float4*)(emb + wid[qq >> 4] * 64 + ((qq * 4) & 63));
        }
        #pragma unroll
        for (int j = 0; j < 2; j++) {
            int qq = tid + j * 256, el = qq * 4;
            *(float4*)(flat + FLAT_SZ + (el >> 5) * FLAT_STRIDE + (el & 31)) = gv[j];
        }
    }
    __syncthreads();

    #pragma unroll 1
    for (int w = 0; w < WPC; w++) {
        // prefetch gather for word w+2
        const bool pf = (w < WPC - 2);
        float4 pv[2];
        if (pf) {
            const int* wid = ids + (word0 + w + 2) * 32;
            #pragma unroll
            for (int j = 0; j < 2; j++) {
                int qq = tid + j * 256;
                pv[j] = *(const float4*)(emb + wid[qq >> 4] * 64 + ((qq * 4) & 63));
            }
        }

        float acc[3][4][4] = {};             // [k][nt][c0..c3]
        const char* xb  = smem + (w & 1) * XFS_BUF + lane * 48;
        char*       xN  = smem + ((w + 1) & 1) * XFS_BUF;
        const float* flN = flat + ((w + 1) & 1) * FLAT_SZ;

        uint4 blo = *(const uint4*)(xb);
        uint4 bhi = *(const uint4*)(xb + 16);

        #pragma unroll
        for (int kt = 0; kt < 8; kt++) {
            uint4 clo = blo, chi = bhi;
            if (kt < 7) {
                blo = *(const uint4*)(xb + (kt + 1) * XFS_KT);
                bhi = *(const uint4*)(xb + (kt + 1) * XFS_KT + 16);
            }
            if (kt == 3 && w < WPC - 1)      // build word w+1 under MMA cover
                build_pair(xN, flN, wu, lane);
            const uint32_t b0[4] = {clo.x, clo.y, clo.z, clo.w};
            const uint32_t b1[4] = {chi.x, chi.y, chi.z, chi.w};
            #pragma unroll
            for (int k = 0; k < 3; k++)
                #pragma unroll
                for (int nt = 0; nt < 4; nt++)
                    asm volatile(
                        "mma.sync.aligned.m16n8k8.row.col.f32.tf32.tf32.f32 "
                        "{%0,%1,%2,%3},{%4,%5,%6,%7},{%8,%9},{%0,%1,%2,%3};"
                        : "+f"(acc[k][nt][0]), "+f"(acc[k][nt][1]),
                          "+f"(acc[k][nt][2]), "+f"(acc[k][nt][3])
                        : "r"(a[k][kt].x), "r"(a[k][kt].y),
                          "r"(a[k][kt].z), "r"(a[k][kt].w),
                          "r"(b0[nt]), "r"(b1[nt]));
        }

        // ---- epilogue: Y[t] = Z0[t] + Z1[t+1] + Z2[t+2], max over t<30 ----
        const int srcl = (lane & ~3) | ((q + 1) & 3);
        float nB0l[4], nC0l[4], nC1l[4], nB0h[4], nC0h[4], nC1h[4];
        #pragma unroll
        for (int nt = 0; nt < 4; nt++) {
            nB0l[nt] = __shfl_sync(0xffffffffu, acc[1][nt][0], srcl);
            nC0l[nt] = __shfl_sync(0xffffffffu, acc[2][nt][0], srcl);
            nC1l[nt] = __shfl_sync(0xffffffffu, acc[2][nt][1], srcl);
            nB0h[nt] = __shfl_sync(0xffffffffu, acc[1][nt][2], srcl);
            nC0h[nt] = __shfl_sync(0xffffffffu, acc[2][nt][2], srcl);
            nC1h[nt] = __shfl_sync(0xffffffffu, acc[2][nt][3], srcl);
        }
        const bool q3 = (q == 3);
        float mxl = -3.0e38f, mxh = -3.0e38f;
        #pragma unroll
        for (int nt = 0; nt < 4; nt++) {
            if (nt == 3 && q3) break;        // t0=30/31 invalid
            float c0l = q3 ? nC0l[(nt + 1) & 3] : nC0l[nt];
            float c1l = q3 ? nC1l[(nt + 1) & 3] : nC1l[nt];
            float b0l = q3 ? nB0l[(nt + 1) & 3] : nB0l[nt];
            float c0h = q3 ? nC0h[(nt + 1) & 3] : nC0h[nt];
            float c1h = q3 ? nC1h[(nt + 1) & 3] : nC1h[nt];
            float b0h = q3 ? nB0h[(nt + 1) & 3] : nB0h[nt];
            float Yel = acc[0][nt][0] + acc[1][nt][1] + c0l;   // t = 8nt+2q
            float Yol = acc[0][nt][1] + b0l + c1l;             // t+1
            float Yeh = acc[0][nt][2] + acc[1][nt][3] + c0h;
            float Yoh = acc[0][nt][3] + b0h + c1h;
            mxl = fmaxf(mxl, fmaxf(Yel, Yol));
            mxh = fmaxf(mxh, fmaxf(Yeh, Yoh));
        }
        mxl = fmaxf(mxl, __shfl_xor_sync(0xffffffffu, mxl, 1));
        mxl = fmaxf(mxl, __shfl_xor_sync(0xffffffffu, mxl, 2));
        mxh = fmaxf(mxh, __shfl_xor_sync(0xffffffffu, mxh, 1));
        mxh = fmaxf(mxh, __shfl_xor_sync(0xffffffffu, mxh, 2));
        const int word = word0 + w;
        if (q == 0)      out[(size_t)word * 128 + wu * 16 + g]     = mxl + blo_b;
        else if (q == 1) out[(size_t)word * 128 + wu * 16 + g + 8] = mxh + bhi_b;

        // flat[w&1] <- word w+2 (buffer free since build(w) ran last word)
        if (pf) {
            #pragma unroll
            for (int j = 0; j < 2; j++) {
                int qq = tid + j * 256, el = qq * 4;
                *(float4*)(flat + (w & 1) * FLAT_SZ
                           + (el >> 5) * FLAT_STRIDE + (el & 31)) = pv[j];
            }
        }
        __syncthreads();
    }
}

extern "C" void kernel_launch(void* const* d_in, const int* in_sizes, int n_in,
                              void* d_out, int out_size) {
    const int*   ids  = (const int*)d_in[0];
    const float* emb  = (const float*)d_in[1];
    const float* wg   = (const float*)d_in[2];
    const float* bias = (const float*)d_in[3];
    float*       out  = (float*)d_out;

    charconv_hmma4<<<GRID, THREADS, SMEM_TOTAL>>>(ids, wg, emb, bias, out);
}

// round 10
// speedup vs baseline: 1.1484x; 1.1484x over previous
#include <cuda_runtime.h>
#include <cstdint>

// CharEmb via mma.sync m16n8k8 tf32, v5:
//   3 GEMMs sharing one B (as v4), but A-fragments pre-reordered into a
//   __device__ scratch by a prep kernel, then streamed per-kt via LDG.128
//   (L1-resident). Cuts regs 202 -> ~110 => 2 CTAs/SM (occ 25%), which fills
//   the tensor-idle gaps that capped v4 at 37% tensor utilization.

static constexpr int WORDS   = 16384;
static constexpr int WPC     = 16;
static constexpr int GRID    = WORDS / WPC;   // 1024
static constexpr int THREADS = 256;           // 8 warps x 16 filters

static constexpr int FLAT_STRIDE = 36;                 // floats per G row
static constexpr int FLAT_SZ     = 64 * FLAT_STRIDE;   // 2304 floats
static constexpr int XFS_KT      = 32 * 48;            // bytes per kt slot row
static constexpr int XFS_BUF     = 8 * XFS_KT;         // 12288 B
static constexpr int FLAT_OFF    = 2 * XFS_BUF;        // 24576
static constexpr int SMEM_TOTAL  = FLAT_OFF + 2 * FLAT_SZ * 4;  // 43008 B

// A fragments: [wu(8)][kt(8)][k(3)][lane(32)][c(4)] tf32 bits = 96KB
__device__ uint32_t g_afrag[8 * 8 * 3 * 32 * 4];

__device__ __forceinline__ uint32_t f2tf32(float f) {
    uint32_t r; asm("cvt.rn.tf32.f32 %0, %1;" : "=r"(r) : "f"(f)); return r;
}
struct U4 { uint32_t x, y, z, w; };

__global__ __launch_bounds__(256) void prep_afrag(const float* __restrict__ wg) {
    int idx = blockIdx.x * 256 + threadIdx.x;     // 0..24575
    int c  = idx & 3;
    int l  = (idx >> 2) & 31;
    int k  = (idx >> 7) % 3;
    int kt = (idx / (4 * 32 * 3)) & 7;
    int wu = idx / (4 * 32 * 3 * 8);
    int f  = wu * 16 + (l >> 2) + ((c & 1) << 3);
    int i  = 8 * kt + (l & 3) + ((c >> 1) << 2);
    g_afrag[idx] = f2tf32(wg[f * 192 + i * 3 + k]);
}

// one (kt, lane) B pair: b0[nt] = G[8kt+(l&3)][8nt+(l>>2)], b1 = +4 rows
__device__ __forceinline__ void build_pair(char* __restrict__ xbuf,
                                           const float* __restrict__ fl,
                                           int kt, int l) {
    const float* p0 = fl + (8 * kt + (l & 3)) * FLAT_STRIDE + (l >> 2);
    const float* p1 = p0 + 4 * FLAT_STRIDE;
    uint4 lo, hi;
    lo.x = f2tf32(p0[0]);  lo.y = f2tf32(p0[8]);
    lo.z = f2tf32(p0[16]); lo.w = f2tf32(p0[24]);
    hi.x = f2tf32(p1[0]);  hi.y = f2tf32(p1[8]);
    hi.z = f2tf32(p1[16]); hi.w = f2tf32(p1[24]);
    *(uint4*)(xbuf + kt * XFS_KT + l * 48)      = lo;
    *(uint4*)(xbuf + kt * XFS_KT + l * 48 + 16) = hi;
}

__global__ __launch_bounds__(THREADS, 2) void charconv_hmma5(
    const int* __restrict__ ids,    // [WORDS][32]
    const float* __restrict__ emb,  // [101][64]
    const float* __restrict__ bias, // [128]
    float* __restrict__ out)        // [WORDS][128]
{
    extern __shared__ char smem[];
    float* flat = (float*)(smem + FLAT_OFF);

    const int tid  = threadIdx.x;
    const int wu   = tid >> 5, lane = tid & 31;
    const int q    = lane & 3, g = lane >> 2;
    const int word0 = blockIdx.x * WPC;

    // gather word0 / word1 into flat
    {
        const int* wid = ids + word0 * 32;
        #pragma unroll
        for (int j = 0; j < 2; j++) {
            int qq = tid + j * 256, el = qq * 4;
            float4 v = *(const float4*)(emb + wid[qq >> 4] * 64 + (el & 63));
            *(float4*)(flat + (el >> 5) * FLAT_STRIDE + (el & 31)) = v;
        }
    }
    __syncthreads();
    build_pair(smem, flat, wu, lane);
    {
        const int* wid = ids + (word0 + 1) * 32;
        #pragma unroll
        for (int j = 0; j < 2; j++) {
            int qq = tid + j * 256, el = qq * 4;
            float4 v = *(const float4*)(emb + wid[qq >> 4] * 64 + (el & 63));
            *(float4*)(flat + FLAT_SZ + (el >> 5) * FLAT_STRIDE + (el & 31)) = v;
        }
    }
    __syncthreads();

    const float blo_b = bias[wu * 16 + g];
    const float bhi_b = bias[wu * 16 + g + 8];
    const uint4* ap = ((const uint4*)g_afrag) + wu * 768 + lane;

    #pragma unroll 1
    for (int w = 0; w < WPC; w++) {
        const bool pf = (w < WPC - 2);
        float4 pv[2];
        if (pf) {
            const int* wid = ids + (word0 + w + 2) * 32;
            #pragma unroll
            for (int j = 0; j < 2; j++) {
                int qq = tid + j * 256;
                pv[j] = *(const float4*)(emb + wid[qq >> 4] * 64 + ((qq * 4) & 63));
            }
        }

        float acc[3][4][4] = {};             // [k][nt][c0..c3]
        const char* xb  = smem + (w & 1) * XFS_BUF + lane * 48;
        char*       xN  = smem + ((w + 1) & 1) * XFS_BUF;
        const float* flN = flat + ((w + 1) & 1) * FLAT_SZ;

        uint4 blo = *(const uint4*)(xb);
        uint4 bhi = *(const uint4*)(xb + 16);
        uint4 a0 = __ldg(ap), a1 = __ldg(ap + 32), a2 = __ldg(ap + 64);

        #pragma unroll
        for (int kt = 0; kt < 8; kt++) {
            uint4 clo = blo, chi = bhi;
            U4 aa[3] = {{a0.x, a0.y, a0.z, a0.w},
                        {a1.x, a1.y, a1.z, a1.w},
                        {a2.x, a2.y, a2.z, a2.w}};
            if (kt < 7) {
                blo = *(const uint4*)(xb + (kt + 1) * XFS_KT);
                bhi = *(const uint4*)(xb + (kt + 1) * XFS_KT + 16);
                a0 = __ldg(ap + (kt + 1) * 96);
                a1 = __ldg(ap + (kt + 1) * 96 + 32);
                a2 = __ldg(ap + (kt + 1) * 96 + 64);
            }
            if (kt == 3 && w < WPC - 1)      // build word w+1 under MMA cover
                build_pair(xN, flN, wu, lane);
            const uint32_t b0[4] = {clo.x, clo.y, clo.z, clo.w};
            const uint32_t b1[4] = {chi.x, chi.y, chi.z, chi.w};
            #pragma unroll
            for (int k = 0; k < 3; k++)
                #pragma unroll
                for (int nt = 0; nt < 4; nt++)
                    asm volatile(
                        "mma.sync.aligned.m16n8k8.row.col.f32.tf32.tf32.f32 "
                        "{%0,%1,%2,%3},{%4,%5,%6,%7},{%8,%9},{%0,%1,%2,%3};"
                        : "+f"(acc[k][nt][0]), "+f"(acc[k][nt][1]),
                          "+f"(acc[k][nt][2]), "+f"(acc[k][nt][3])
                        : "r"(aa[k].x), "r"(aa[k].y),
                          "r"(aa[k].z), "r"(aa[k].w),
                          "r"(b0[nt]), "r"(b1[nt]));
        }

        // store prefetched flat now (frees pv regs before epilogue)
        if (pf) {
            #pragma unroll
            for (int j = 0; j < 2; j++) {
                int qq = tid + j * 256, el = qq * 4;
                *(float4*)(flat + (w & 1) * FLAT_SZ
                           + (el >> 5) * FLAT_STRIDE + (el & 31)) = pv[j];
            }
        }

        // ---- epilogue: Y[t] = Z0[t] + Z1[t+1] + Z2[t+2], max over t<30 ----
        const int srcl = (lane & ~3) | ((q + 1) & 3);
        float nB0l[4], nC0l[4], nC1l[4], nB0h[4], nC0h[4], nC1h[4];
        #pragma unroll
        for (int nt = 0; nt < 4; nt++) {
            nB0l[nt] = __shfl_sync(0xffffffffu, acc[1][nt][0], srcl);
            nC0l[nt] = __shfl_sync(0xffffffffu, acc[2][nt][0], srcl);
            nC1l[nt] = __shfl_sync(0xffffffffu, acc[2][nt][1], srcl);
            nB0h[nt] = __shfl_sync(0xffffffffu, acc[1][nt][2], srcl);
            nC0h[nt] = __shfl_sync(0xffffffffu, acc[2][nt][2], srcl);
            nC1h[nt] = __shfl_sync(0xffffffffu, acc[2][nt][3], srcl);
        }
        const bool q3 = (q == 3);
        float mxl = -3.0e38f, mxh = -3.0e38f;
        #pragma unroll
        for (int nt = 0; nt < 4; nt++) {
            if (nt == 3 && q3) break;        // t0=30/31 invalid
            float c0l = q3 ? nC0l[(nt + 1) & 3] : nC0l[nt];
            float c1l = q3 ? nC1l[(nt + 1) & 3] : nC1l[nt];
            float b0l = q3 ? nB0l[(nt + 1) & 3] : nB0l[nt];
            float c0h = q3 ? nC0h[(nt + 1) & 3] : nC0h[nt];
            float c1h = q3 ? nC1h[(nt + 1) & 3] : nC1h[nt];
            float b0h = q3 ? nB0h[(nt + 1) & 3] : nB0h[nt];
            float Yel = acc[0][nt][0] + acc[1][nt][1] + c0l;   // t = 8nt+2q
            float Yol = acc[0][nt][1] + b0l + c1l;             // t+1
            float Yeh = acc[0][nt][2] + acc[1][nt][3] + c0h;
            float Yoh = acc[0][nt][3] + b0h + c1h;
            mxl = fmaxf(mxl, fmaxf(Yel, Yol));
            mxh = fmaxf(mxh, fmaxf(Yeh, Yoh));
        }
        mxl = fmaxf(mxl, __shfl_xor_sync(0xffffffffu, mxl, 1));
        mxl = fmaxf(mxl, __shfl_xor_sync(0xffffffffu, mxl, 2));
        mxh = fmaxf(mxh, __shfl_xor_sync(0xffffffffu, mxh, 1));
        mxh = fmaxf(mxh, __shfl_xor_sync(0xffffffffu, mxh, 2));
        const int word = word0 + w;
        if (q == 0)      out[(size_t)word * 128 + wu * 16 + g]     = mxl + blo_b;
        else if (q == 1) out[(size_t)word * 128 + wu * 16 + g + 8] = mxh + bhi_b;

        __syncthreads();
    }
}

extern "C" void kernel_launch(void* const* d_in, const int* in_sizes, int n_in,
                              void* d_out, int out_size) {
    const int*   ids  = (const int*)d_in[0];
    const float* emb  = (const float*)d_in[1];
    const float* wg   = (const float*)d_in[2];
    const float* bias = (const float*)d_in[3];
    float*       out  = (float*)d_out;

    prep_afrag<<<96, 256>>>(wg);
    charconv_hmma5<<<GRID, THREADS, SMEM_TOTAL>>>(ids, emb, bias, out);
}